// round 1
// baseline (speedup 1.0000x reference)
#include <cuda_runtime.h>
#include <math.h>

// ---------------- problem constants ----------------
#define Bc   16
#define Tc   1536
#define Vc   64
#define F1c  16
#define Hc   4
#define FOc  8
#define F2c  32
#define K1c  32
#define K3c  16
#define NG   8          // graphs (t values) per block
#define EMAX 512

// ---------------- device scratch (no allocation allowed) ----------------
__device__ float d_weff[32 * 32];   // [k][ho] (transposed effective conv weights)
__device__ float d_cvec[32];        // effective bias from BN1 shift through W
__device__ float d_scale2[32], d_shift2[32], d_scale3[32], d_shift3[32];
__device__ int   d_off[Vc + 1];
__device__ int   d_srcs[EMAX];
__device__ float d_gbuf[Bc * Tc * F2c];   // g = mean_v(GAT out)+bias, (b,t,f) fp32, 3MB

// ---------------- fast exp (avoid MUFU bottleneck: 31.5M exps) ----------------
// valid for x <= 0 (softmax-shifted), rel err ~3e-6
__device__ __forceinline__ float fast_exp_neg(float x) {
    x = fmaxf(x, -87.0f);
    float y = x * 1.4426950408889634f;   // x * log2(e)
    float n = rintf(y);
    float f = y - n;                      // f in [-0.5, 0.5]
    float p = 1.3333558146428443e-3f;
    p = fmaf(p, f, 9.6181291076284772e-3f);
    p = fmaf(p, f, 5.5504108664821580e-2f);
    p = fmaf(p, f, 2.4022650695910071e-1f);
    p = fmaf(p, f, 6.9314718055994531e-1f);
    p = fmaf(p, f, 1.0f);
    int e = (int)n;
    return p * __int_as_float((e + 127) << 23);
}

// ---------------- setup: fold BN1 into conv1*W, BN2/3 affines, edge CSR ----------------
__global__ void setup_kernel(const float* __restrict__ conv1_w,
                             const float* __restrict__ bn1_g, const float* __restrict__ bn1_b,
                             const float* __restrict__ bn1_m, const float* __restrict__ bn1_v,
                             const float* __restrict__ gat_w,
                             const float* __restrict__ bn2_g, const float* __restrict__ bn2_b,
                             const float* __restrict__ bn2_m, const float* __restrict__ bn2_v,
                             const float* __restrict__ bn3_g, const float* __restrict__ bn3_b,
                             const float* __restrict__ bn3_m, const float* __restrict__ bn3_v,
                             const int* __restrict__ edge_index, int E) {
    __shared__ float sc1[F1c], sh1[F1c];
    int tid = threadIdx.x;
    if (tid < F1c) {
        float s = bn1_g[tid] * rsqrtf(bn1_v[tid] + 1e-5f);
        sc1[tid] = s;
        sh1[tid] = bn1_b[tid] - bn1_m[tid] * s;
    }
    if (tid < F2c) {
        float s2 = bn2_g[tid] * rsqrtf(bn2_v[tid] + 1e-5f);
        d_scale2[tid] = s2; d_shift2[tid] = bn2_b[tid] - bn2_m[tid] * s2;
        float s3 = bn3_g[tid] * rsqrtf(bn3_v[tid] + 1e-5f);
        d_scale3[tid] = s3; d_shift3[tid] = bn3_b[tid] - bn3_m[tid] * s3;
    }
    __syncthreads();
    // weff[k][ho] = sum_f gat_w[f,ho] * scale1[f] * conv1_w[f,k]
    for (int i = tid; i < K1c * 32; i += blockDim.x) {
        int k = i >> 5, ho = i & 31;
        float s = 0.f;
        #pragma unroll
        for (int f = 0; f < F1c; f++)
            s = fmaf(gat_w[f * 32 + ho] * sc1[f], conv1_w[f * K1c + k], s);
        d_weff[i] = s;
    }
    if (tid < 32) {
        float s = 0.f;
        #pragma unroll
        for (int f = 0; f < F1c; f++) s = fmaf(gat_w[f * 32 + tid], sh1[f], s);
        d_cvec[tid] = s;
    }
    if (tid == 0) {
        // CSR over dst
        int cnt[Vc];
        for (int v = 0; v < Vc; v++) cnt[v] = 0;
        const int* src = edge_index;
        const int* dst = edge_index + E;
        for (int e = 0; e < E && e < EMAX; e++) cnt[dst[e]]++;
        int off = 0;
        for (int v = 0; v < Vc; v++) { d_off[v] = off; off += cnt[v]; cnt[v] = 0; }
        d_off[Vc] = off;
        for (int e = 0; e < E && e < EMAX; e++) {
            int d = dst[e];
            d_srcs[d_off[d] + cnt[d]++] = src[e];
        }
    }
}

// ---------------- main: fused conv(+BN1+GAT linear) + GAT attention + node mean ----------------
// grid: B * (T/NG) blocks of 256 threads; block = (b, 8 consecutive t)
// smem layout (floats):
//  xs[64*40] | wefft[1024] | cvec[32] | asrc[32] | adst[32] | bias[32]
//  hbuf[NG*64*32] | es[NG*256] | ed[NG*256] | (ints) off[65] srcs[EMAX]
#define XS_F     (64 * 40)
#define SM_FLOATS (XS_F + 1024 + 32 * 4 + NG * 2048 + NG * 256 * 2)
#define MAIN_SMEM (SM_FLOATS * 4 + (Vc + 1 + EMAX) * 4)

__global__ void __launch_bounds__(256, 2)
main_kernel(const float* __restrict__ x,
            const float* __restrict__ asrc_g,
            const float* __restrict__ adst_g,
            const float* __restrict__ bias_g,
            int E) {
    extern __shared__ float sm[];
    float* xs    = sm;
    float* wefft = xs + XS_F;
    float* cvec  = wefft + 1024;
    float* sasrc = cvec + 32;
    float* sadst = sasrc + 32;
    float* sbias = sadst + 32;
    float* hbuf  = sbias + 32;                 // [g][v][ho]
    float* es_s  = hbuf + NG * 2048;           // [g][v*4+head]
    float* ed_s  = es_s + NG * 256;
    int*   soff  = (int*)(ed_s + NG * 256);
    int*   ssrc  = soff + (Vc + 1);

    const int tid = threadIdx.x;
    const int bx  = blockIdx.x;
    const int b   = bx / (Tc / NG);
    const int t0  = (bx % (Tc / NG)) * NG;

    // cooperative loads
    for (int i = tid; i < 1024; i += 256) wefft[i] = d_weff[i];
    if (tid < 32) {
        cvec[tid]  = d_cvec[tid];
        sasrc[tid] = asrc_g[tid];
        sadst[tid] = adst_g[tid];
        sbias[tid] = bias_g[tid];
    }
    for (int i = tid; i < Vc + 1; i += 256) soff[i] = d_off[i];
    for (int i = tid; i < E; i += 256) ssrc[i] = d_srcs[i];
    for (int idx = tid; idx < 64 * 40; idx += 256) {
        int v = idx / 40, j = idx - v * 40;
        int t = t0 - 15 + j;
        float val = 0.f;
        if (j < NG + 31 && t >= 0 && t < Tc) val = x[(b * Vc + v) * Tc + t];
        xs[idx] = val;
    }
    __syncthreads();

    // ---- fused conv: h[g][v][ho] = c[ho] + sum_k weff[ho][k] * xs[v][g+k] ----
    {
        const int ho = tid & 31;
        const int vslot = tid >> 5;
        float w[K1c];
        #pragma unroll
        for (int k = 0; k < K1c; k++) w[k] = wefft[k * 32 + ho];
        const float cv = cvec[ho];
        for (int i = 0; i < 8; i++) {
            const int v = vslot * 8 + i;
            const float* xr = xs + v * 40;
            float acc[NG];
            #pragma unroll
            for (int g = 0; g < NG; g++) acc[g] = cv;
            #pragma unroll
            for (int k = 0; k < K1c; k++) {
                const float wv = w[k];
                #pragma unroll
                for (int g = 0; g < NG; g++) acc[g] = fmaf(wv, xr[g + k], acc[g]);
            }
            #pragma unroll
            for (int g = 0; g < NG; g++) hbuf[(g * 64 + v) * 32 + ho] = acc[g];
        }
    }
    __syncthreads();

    // ---- GAT: one warp per graph ----
    {
        const int warp = tid >> 5, lane = tid & 31;
        const int gg = warp;
        float* h  = hbuf + gg * 2048;
        float* es = es_s + gg * 256;
        float* ed = ed_s + gg * 256;

        // es/ed: 256 (v,head) pairs
        #pragma unroll
        for (int i = 0; i < 8; i++) {
            int p = lane + 32 * i;
            int head = p & 3, v = p >> 2;
            const float* hv = h + v * 32 + head * 8;
            const float* as = sasrc + head * 8;
            const float* ad = sadst + head * 8;
            float se = 0.f, sd = 0.f;
            #pragma unroll
            for (int o = 0; o < 8; o++) {
                float hx = hv[o];
                se = fmaf(hx, as[o], se);
                sd = fmaf(hx, ad[o], sd);
            }
            es[p] = se; ed[p] = sd;
        }
        __syncwarp();

        // attention + aggregation + running node-mean
        float macc[8];
        #pragma unroll
        for (int o = 0; o < 8; o++) macc[o] = 0.f;
        const int head = lane & 3;
        for (int i = 0; i < 8; i++) {
            const int d = (lane >> 2) + 8 * i;
            const float edv = ed[d * 4 + head];
            const int beg = soff[d], end = soff[d + 1];
            float m = -1e30f;
            for (int e = beg; e < end; e++) {
                float ev = es[ssrc[e] * 4 + head] + edv;
                ev = ev > 0.f ? ev : 0.2f * ev;
                m = fmaxf(m, ev);
            }
            float den = 0.f;
            float acc[8];
            #pragma unroll
            for (int o = 0; o < 8; o++) acc[o] = 0.f;
            for (int e = beg; e < end; e++) {
                int s = ssrc[e];
                float ev = es[s * 4 + head] + edv;
                ev = ev > 0.f ? ev : 0.2f * ev;
                float wexp = fast_exp_neg(ev - m);
                den += wexp;
                const float* hs = h + s * 32 + head * 8;
                #pragma unroll
                for (int o = 0; o < 8; o++) acc[o] = fmaf(wexp, hs[o], acc[o]);
            }
            float inv = 1.0f / den;
            #pragma unroll
            for (int o = 0; o < 8; o++) macc[o] = fmaf(acc[o], inv, macc[o]);
        }
        // reduce node mean across the 8 lanes that share `head`
        #pragma unroll
        for (int o = 0; o < 8; o++) {
            macc[o] += __shfl_xor_sync(0xffffffffu, macc[o], 4);
            macc[o] += __shfl_xor_sync(0xffffffffu, macc[o], 8);
            macc[o] += __shfl_xor_sync(0xffffffffu, macc[o], 16);
        }
        if (lane < 4) {
            const int t = t0 + gg;
            float* gout = d_gbuf + (b * Tc + t) * 32 + head * 8;
            #pragma unroll
            for (int o = 0; o < 8; o++)
                gout[o] = macc[o] * (1.0f / 64.0f) + sbias[head * 8 + o];
        }
    }
}

// ---------------- tail: BN2 + ELU + pool8 + conv3 + BN3 + ELU + pool4 ----------------
// grid: (B, 8) blocks, each covers 24 conv-t positions (6 outputs)
#define TP 192
#define TAIL_SMEM ((F2c * F2c * K3c + F2c * 40 + F2c * 24) * 4)

__global__ void __launch_bounds__(256)
tail_kernel(const float* __restrict__ conv3_w, float* __restrict__ out) {
    extern __shared__ float sm[];
    float* w3s   = sm;                       // [fo][fi][k] 32*32*16
    float* ptile = w3s + F2c * F2c * K3c;    // [fi][j] 32*40 (j=0 <-> tc0-7)
    float* ytile = ptile + F2c * 40;         // [fo][tcl] 32*24

    const int tid = threadIdx.x;
    const int b = blockIdx.x;
    const int tile = blockIdx.y;
    const int tc0 = tile * 24;

    for (int i = tid; i < F2c * F2c * K3c; i += 256) w3s[i] = conv3_w[i];
    // pooled, BN2+ELU'd input window (with conv halo)
    for (int i = tid; i < F2c * 40; i += 256) {
        int fi = i & 31, j = i >> 5;
        int tc = tc0 - 7 + j;
        float val = 0.f;
        if (j < 39 && tc >= 0 && tc < TP) {
            float scv = d_scale2[fi], shv = d_shift2[fi];
            float s = 0.f;
            #pragma unroll
            for (int r = 0; r < 8; r++) {
                float gv = fmaf(scv, d_gbuf[(b * Tc + tc * 8 + r) * 32 + fi], shv);
                s += gv > 0.f ? gv : (__expf(gv) - 1.f);
            }
            val = s * 0.125f;
        }
        ptile[fi * 40 + j] = val;
    }
    __syncthreads();

    // conv3 + BN3 + ELU at 32 fo x 24 tc
    for (int oidx = tid; oidx < F2c * 24; oidx += 256) {
        int fo = oidx / 24;
        int tcl = oidx - fo * 24;
        float acc = 0.f;
        for (int fi = 0; fi < F2c; fi++) {
            const float* wr = w3s + (fo * 32 + fi) * 16;
            const float* pr = ptile + fi * 40 + tcl;
            #pragma unroll
            for (int k = 0; k < K3c; k++) acc = fmaf(wr[k], pr[k], acc);
        }
        float z = fmaf(d_scale3[fo], acc, d_shift3[fo]);
        z = z > 0.f ? z : (__expf(z) - 1.f);
        ytile[fo * 24 + tcl] = z;
    }
    __syncthreads();

    // pool4 -> output (B, 32, 1, 48)
    for (int i = tid; i < F2c * 6; i += 256) {
        int fo = i / 6, tl = i - fo * 6;
        const float* yr = ytile + fo * 24 + tl * 4;
        float s = 0.25f * (yr[0] + yr[1] + yr[2] + yr[3]);
        out[(b * 32 + fo) * 48 + tile * 6 + tl] = s;
    }
}

// ---------------- launch ----------------
extern "C" void kernel_launch(void* const* d_in, const int* in_sizes, int n_in,
                              void* d_out, int out_size) {
    const float* x        = (const float*)d_in[0];
    const float* conv1_w  = (const float*)d_in[1];
    const float* bn1_g    = (const float*)d_in[2];
    const float* bn1_b    = (const float*)d_in[3];
    const float* bn1_m    = (const float*)d_in[4];
    const float* bn1_v    = (const float*)d_in[5];
    const float* gat_w    = (const float*)d_in[6];
    const float* gat_asrc = (const float*)d_in[7];
    const float* gat_adst = (const float*)d_in[8];
    const float* gat_bias = (const float*)d_in[9];
    const float* bn2_g    = (const float*)d_in[10];
    const float* bn2_b    = (const float*)d_in[11];
    const float* bn2_m    = (const float*)d_in[12];
    const float* bn2_v    = (const float*)d_in[13];
    const float* conv3_w  = (const float*)d_in[14];
    const float* bn3_g    = (const float*)d_in[15];
    const float* bn3_b    = (const float*)d_in[16];
    const float* bn3_m    = (const float*)d_in[17];
    const float* bn3_v    = (const float*)d_in[18];
    const int*   edge_idx = (const int*)d_in[19];
    int E = in_sizes[19] / 2;
    if (E > EMAX) E = EMAX;

    cudaFuncSetAttribute(main_kernel, cudaFuncAttributeMaxDynamicSharedMemorySize, MAIN_SMEM);
    cudaFuncSetAttribute(tail_kernel, cudaFuncAttributeMaxDynamicSharedMemorySize, TAIL_SMEM);

    setup_kernel<<<1, 256>>>(conv1_w, bn1_g, bn1_b, bn1_m, bn1_v, gat_w,
                             bn2_g, bn2_b, bn2_m, bn2_v,
                             bn3_g, bn3_b, bn3_m, bn3_v, edge_idx, E);
    main_kernel<<<Bc * (Tc / NG), 256, MAIN_SMEM>>>(x, gat_asrc, gat_adst, gat_bias, E);
    tail_kernel<<<dim3(Bc, 8), 256, TAIL_SMEM>>>(conv3_w, (float*)d_out);
}

// round 2
// speedup vs baseline: 1.0545x; 1.0545x over previous
#include <cuda_runtime.h>
#include <math.h>

// ---------------- problem constants ----------------
#define Bc   16
#define Tc   1536
#define Vc   64
#define F1c  16
#define Hc   4
#define FOc  8
#define F2c  32
#define K1c  32
#define K3c  16
#define NG   8          // graphs (t values) per block
#define EMAX 512

// ---------------- device scratch (no allocation allowed) ----------------
__device__ float d_weff[32 * 32];   // [k][ho]
__device__ float d_cvec[32];
__device__ float d_scale2[32], d_shift2[32], d_scale3[32], d_shift3[32];
__device__ int   d_off[Vc + 1];
__device__ int   d_srcs[EMAX];
__device__ float d_gbuf[Bc * Tc * F2c];

// ---------------- packed f32x2 helpers (FFMA2: 2 FMA / instr on sm_103a) ----
typedef unsigned long long ull;
__device__ __forceinline__ ull pack2(float lo, float hi) {
    ull r;
    asm("mov.b64 %0, {%1, %2};" : "=l"(r) : "f"(lo), "f"(hi));
    return r;
}
__device__ __forceinline__ void fma2(ull& d, ull a, ull b) {
    asm("fma.rn.f32x2 %0, %1, %2, %0;" : "+l"(d) : "l"(a), "l"(b));
}
__device__ __forceinline__ void unpack2(ull v, float& lo, float& hi) {
    asm("mov.b64 {%0, %1}, %2;" : "=f"(lo), "=f"(hi) : "l"(v));
}

// ---------------- fast exp (x <= 0), rel err ~3e-6 ----------------
__device__ __forceinline__ float fast_exp_neg(float x) {
    x = fmaxf(x, -87.0f);
    float y = x * 1.4426950408889634f;
    float n = rintf(y);
    float f = y - n;
    float p = 1.3333558146428443e-3f;
    p = fmaf(p, f, 9.6181291076284772e-3f);
    p = fmaf(p, f, 5.5504108664821580e-2f);
    p = fmaf(p, f, 2.4022650695910071e-1f);
    p = fmaf(p, f, 6.9314718055994531e-1f);
    p = fmaf(p, f, 1.0f);
    int e = (int)n;
    return p * __int_as_float((e + 127) << 23);
}

// ---------------- setup: fold BN1 into conv1*W, BN2/3 affines, edge CSR ----
__global__ void setup_kernel(const float* __restrict__ conv1_w,
                             const float* __restrict__ bn1_g, const float* __restrict__ bn1_b,
                             const float* __restrict__ bn1_m, const float* __restrict__ bn1_v,
                             const float* __restrict__ gat_w,
                             const float* __restrict__ bn2_g, const float* __restrict__ bn2_b,
                             const float* __restrict__ bn2_m, const float* __restrict__ bn2_v,
                             const float* __restrict__ bn3_g, const float* __restrict__ bn3_b,
                             const float* __restrict__ bn3_m, const float* __restrict__ bn3_v,
                             const int* __restrict__ edge_index, int E) {
    __shared__ float sc1[F1c], sh1[F1c];
    __shared__ int scnt[Vc], soff[Vc + 1];
    int tid = threadIdx.x;
    if (tid < F1c) {
        float s = bn1_g[tid] * rsqrtf(bn1_v[tid] + 1e-5f);
        sc1[tid] = s;
        sh1[tid] = bn1_b[tid] - bn1_m[tid] * s;
    }
    if (tid < F2c) {
        float s2 = bn2_g[tid] * rsqrtf(bn2_v[tid] + 1e-5f);
        d_scale2[tid] = s2; d_shift2[tid] = bn2_b[tid] - bn2_m[tid] * s2;
        float s3 = bn3_g[tid] * rsqrtf(bn3_v[tid] + 1e-5f);
        d_scale3[tid] = s3; d_shift3[tid] = bn3_b[tid] - bn3_m[tid] * s3;
    }
    __syncthreads();
    for (int i = tid; i < K1c * 32; i += blockDim.x) {
        int k = i >> 5, ho = i & 31;
        float s = 0.f;
        #pragma unroll
        for (int f = 0; f < F1c; f++)
            s = fmaf(gat_w[f * 32 + ho] * sc1[f], conv1_w[f * K1c + k], s);
        d_weff[i] = s;
    }
    if (tid < 32) {
        float s = 0.f;
        #pragma unroll
        for (int f = 0; f < F1c; f++) s = fmaf(gat_w[f * 32 + tid], sh1[f], s);
        d_cvec[tid] = s;
    }
    // parallel deterministic CSR: thread v scans the edge list for dst==v
    const int* src = edge_index;
    const int* dst = edge_index + E;
    if (tid < Vc) {
        int c = 0;
        for (int e = 0; e < E; e++) c += (dst[e] == tid);
        scnt[tid] = c;
    }
    __syncthreads();
    if (tid == 0) {
        int off = 0;
        for (int v = 0; v < Vc; v++) { soff[v] = off; off += scnt[v]; }
        soff[Vc] = off;
    }
    __syncthreads();
    if (tid <= Vc) d_off[tid] = soff[tid];
    if (tid < Vc) {
        int p = soff[tid];
        for (int e = 0; e < E; e++)
            if (dst[e] == tid) d_srcs[p++] = src[e];
    }
}

// ---------------- main: fused conv(+BN1+GAT linear) + GAT + node mean ------
#define XS_F     (64 * 40)
#define SM_FLOATS (XS_F + 1024 + 32 * 4 + NG * 2048 + NG * 256 * 2)
#define MAIN_SMEM (SM_FLOATS * 4 + (Vc + 1 + EMAX) * 4)

__global__ void __launch_bounds__(256)
main_kernel(const float* __restrict__ x,
            const float* __restrict__ asrc_g,
            const float* __restrict__ adst_g,
            const float* __restrict__ bias_g,
            int E) {
    extern __shared__ float sm[];
    float* xs    = sm;
    float* wefft = xs + XS_F;
    float* cvec  = wefft + 1024;
    float* sasrc = cvec + 32;
    float* sadst = sasrc + 32;
    float* sbias = sadst + 32;
    float* hbuf  = sbias + 32;                 // [g][v][ho]
    float* es_s  = hbuf + NG * 2048;           // [g][v*4+head]
    float* ed_s  = es_s + NG * 256;
    int*   soff  = (int*)(ed_s + NG * 256);
    int*   ssrc  = soff + (Vc + 1);

    const int tid = threadIdx.x;
    const int bx  = blockIdx.x;
    const int b   = bx / (Tc / NG);
    const int t0  = (bx % (Tc / NG)) * NG;

    for (int i = tid; i < 1024; i += 256) wefft[i] = d_weff[i];
    if (tid < 32) {
        cvec[tid]  = d_cvec[tid];
        sasrc[tid] = asrc_g[tid];
        sadst[tid] = adst_g[tid];
        sbias[tid] = bias_g[tid];
    }
    for (int i = tid; i < Vc + 1; i += 256) soff[i] = d_off[i];
    for (int i = tid; i < E; i += 256) ssrc[i] = d_srcs[i];
    for (int idx = tid; idx < 64 * 40; idx += 256) {
        int v = idx / 40, j = idx - v * 40;
        int t = t0 - 15 + j;
        float val = 0.f;
        if (j < NG + 31 && t >= 0 && t < Tc) val = x[(b * Vc + v) * Tc + t];
        xs[idx] = val;
    }
    __syncthreads();

    // ---- fused conv via FFMA2: h[g][v][ho] = c[ho] + sum_k w[ho][k]*x[v][g+k]
    {
        const int ho = tid & 31;
        const int vslot = tid >> 5;
        float w[K1c];
        #pragma unroll
        for (int k = 0; k < K1c; k++) w[k] = wefft[k * 32 + ho];
        const float cv = cvec[ho];
        for (int i = 0; i < 8; i++) {
            const int v = vslot * 8 + i;
            const float4* xr4 = (const float4*)(xs + v * 40);
            // load 40 floats as 10 float4
            float4 xq[10];
            #pragma unroll
            for (int m = 0; m < 10; m++) xq[m] = xr4[m];
            // even-offset pairs pe[j]={x[2j],x[2j+1]}, odd po[j]={x[2j+1],x[2j+2]}
            ull pe[19], po[19];
            #pragma unroll
            for (int m = 0; m < 10; m++) {
                if (2 * m     < 19) pe[2 * m]     = pack2(xq[m].x, xq[m].y);
                if (2 * m + 1 < 19) pe[2 * m + 1] = pack2(xq[m].z, xq[m].w);
                if (2 * m     < 19) po[2 * m]     = pack2(xq[m].y, xq[m].z);
                if (2 * m + 1 < 19 && m < 9) po[2 * m + 1] = pack2(xq[m].w, xq[m + 1].x);
            }
            ull acc2[4];
            #pragma unroll
            for (int p = 0; p < 4; p++) acc2[p] = pack2(cv, cv);
            #pragma unroll
            for (int kh = 0; kh < 16; kh++) {
                const ull w0 = pack2(w[2 * kh],     w[2 * kh]);
                const ull w1 = pack2(w[2 * kh + 1], w[2 * kh + 1]);
                #pragma unroll
                for (int p = 0; p < 4; p++) fma2(acc2[p], w0, pe[kh + p]);
                #pragma unroll
                for (int p = 0; p < 4; p++) fma2(acc2[p], w1, po[kh + p]);
            }
            #pragma unroll
            for (int p = 0; p < 4; p++) {
                float lo, hi;
                unpack2(acc2[p], lo, hi);
                hbuf[((2 * p)     * 64 + v) * 32 + ho] = lo;
                hbuf[((2 * p + 1) * 64 + v) * 32 + ho] = hi;
            }
        }
    }
    __syncthreads();

    // ---- GAT: one warp per graph ----
    {
        const int warp = tid >> 5, lane = tid & 31;
        const int gg = warp;
        float* h  = hbuf + gg * 2048;
        float* es = es_s + gg * 256;
        float* ed = ed_s + gg * 256;

        #pragma unroll
        for (int i = 0; i < 8; i++) {
            int p = lane + 32 * i;
            int head = p & 3, v = p >> 2;
            const float* hv = h + v * 32 + head * 8;
            const float* as = sasrc + head * 8;
            const float* ad = sadst + head * 8;
            float se = 0.f, sd = 0.f;
            #pragma unroll
            for (int o = 0; o < 8; o++) {
                float hx = hv[o];
                se = fmaf(hx, as[o], se);
                sd = fmaf(hx, ad[o], sd);
            }
            es[p] = se; ed[p] = sd;
        }
        __syncwarp();

        float macc[8];
        #pragma unroll
        for (int o = 0; o < 8; o++) macc[o] = 0.f;
        const int head = lane & 3;
        for (int i = 0; i < 8; i++) {
            const int d = (lane >> 2) + 8 * i;
            const float edv = ed[d * 4 + head];
            const int beg = soff[d], end = soff[d + 1];
            float m = -1e30f;
            for (int e = beg; e < end; e++) {
                float ev = es[ssrc[e] * 4 + head] + edv;
                ev = ev > 0.f ? ev : 0.2f * ev;
                m = fmaxf(m, ev);
            }
            float den = 0.f;
            float acc[8];
            #pragma unroll
            for (int o = 0; o < 8; o++) acc[o] = 0.f;
            for (int e = beg; e < end; e++) {
                int s = ssrc[e];
                float ev = es[s * 4 + head] + edv;
                ev = ev > 0.f ? ev : 0.2f * ev;
                float wexp = fast_exp_neg(ev - m);
                den += wexp;
                const float* hs = h + s * 32 + head * 8;
                #pragma unroll
                for (int o = 0; o < 8; o++) acc[o] = fmaf(wexp, hs[o], acc[o]);
            }
            float inv = 1.0f / den;
            #pragma unroll
            for (int o = 0; o < 8; o++) macc[o] = fmaf(acc[o], inv, macc[o]);
        }
        #pragma unroll
        for (int o = 0; o < 8; o++) {
            macc[o] += __shfl_xor_sync(0xffffffffu, macc[o], 4);
            macc[o] += __shfl_xor_sync(0xffffffffu, macc[o], 8);
            macc[o] += __shfl_xor_sync(0xffffffffu, macc[o], 16);
        }
        if (lane < 4) {
            const int t = t0 + gg;
            float* gout = d_gbuf + (b * Tc + t) * 32 + head * 8;
            #pragma unroll
            for (int o = 0; o < 8; o++)
                gout[o] = macc[o] * (1.0f / 64.0f) + sbias[head * 8 + o];
        }
    }
}

// ---------------- tail: BN2 + ELU + pool8 + conv3 + BN3 + ELU + pool4 ------
#define TP 192
#define TAIL_SMEM ((F2c * F2c * K3c + F2c * 40 + F2c * 24) * 4)

__global__ void __launch_bounds__(256)
tail_kernel(const float* __restrict__ conv3_w, float* __restrict__ out) {
    extern __shared__ float sm[];
    float* w3s   = sm;
    float* ptile = w3s + F2c * F2c * K3c;
    float* ytile = ptile + F2c * 40;

    const int tid = threadIdx.x;
    const int b = blockIdx.x;
    const int tile = blockIdx.y;
    const int tc0 = tile * 24;

    for (int i = tid; i < F2c * F2c * K3c; i += 256) w3s[i] = conv3_w[i];
    for (int i = tid; i < F2c * 40; i += 256) {
        int fi = i & 31, j = i >> 5;
        int tc = tc0 - 7 + j;
        float val = 0.f;
        if (j < 39 && tc >= 0 && tc < TP) {
            float scv = d_scale2[fi], shv = d_shift2[fi];
            float s = 0.f;
            #pragma unroll
            for (int r = 0; r < 8; r++) {
                float gv = fmaf(scv, d_gbuf[(b * Tc + tc * 8 + r) * 32 + fi], shv);
                s += gv > 0.f ? gv : (__expf(gv) - 1.f);
            }
            val = s * 0.125f;
        }
        ptile[fi * 40 + j] = val;
    }
    __syncthreads();

    for (int oidx = tid; oidx < F2c * 24; oidx += 256) {
        int fo = oidx / 24;
        int tcl = oidx - fo * 24;
        float acc = 0.f;
        for (int fi = 0; fi < F2c; fi++) {
            const float* wr = w3s + (fo * 32 + fi) * 16;
            const float* pr = ptile + fi * 40 + tcl;
            #pragma unroll
            for (int k = 0; k < K3c; k++) acc = fmaf(wr[k], pr[k], acc);
        }
        float z = fmaf(d_scale3[fo], acc, d_shift3[fo]);
        z = z > 0.f ? z : (__expf(z) - 1.f);
        ytile[fo * 24 + tcl] = z;
    }
    __syncthreads();

    for (int i = tid; i < F2c * 6; i += 256) {
        int fo = i / 6, tl = i - fo * 6;
        const float* yr = ytile + fo * 24 + tl * 4;
        float s = 0.25f * (yr[0] + yr[1] + yr[2] + yr[3]);
        out[(b * 32 + fo) * 48 + tile * 6 + tl] = s;
    }
}

// ---------------- launch ----------------
extern "C" void kernel_launch(void* const* d_in, const int* in_sizes, int n_in,
                              void* d_out, int out_size) {
    const float* x        = (const float*)d_in[0];
    const float* conv1_w  = (const float*)d_in[1];
    const float* bn1_g    = (const float*)d_in[2];
    const float* bn1_b    = (const float*)d_in[3];
    const float* bn1_m    = (const float*)d_in[4];
    const float* bn1_v    = (const float*)d_in[5];
    const float* gat_w    = (const float*)d_in[6];
    const float* gat_asrc = (const float*)d_in[7];
    const float* gat_adst = (const float*)d_in[8];
    const float* gat_bias = (const float*)d_in[9];
    const float* bn2_g    = (const float*)d_in[10];
    const float* bn2_b    = (const float*)d_in[11];
    const float* bn2_m    = (const float*)d_in[12];
    const float* bn2_v    = (const float*)d_in[13];
    const float* conv3_w  = (const float*)d_in[14];
    const float* bn3_g    = (const float*)d_in[15];
    const float* bn3_b    = (const float*)d_in[16];
    const float* bn3_m    = (const float*)d_in[17];
    const float* bn3_v    = (const float*)d_in[18];
    const int*   edge_idx = (const int*)d_in[19];
    int E = in_sizes[19] / 2;
    if (E > EMAX) E = EMAX;

    cudaFuncSetAttribute(main_kernel, cudaFuncAttributeMaxDynamicSharedMemorySize, MAIN_SMEM);
    cudaFuncSetAttribute(tail_kernel, cudaFuncAttributeMaxDynamicSharedMemorySize, TAIL_SMEM);

    setup_kernel<<<1, 256>>>(conv1_w, bn1_g, bn1_b, bn1_m, bn1_v, gat_w,
                             bn2_g, bn2_b, bn2_m, bn2_v,
                             bn3_g, bn3_b, bn3_m, bn3_v, edge_idx, E);
    main_kernel<<<Bc * (Tc / NG), 256, MAIN_SMEM>>>(x, gat_asrc, gat_adst, gat_bias, E);
    tail_kernel<<<dim3(Bc, 8), 256, TAIL_SMEM>>>(conv3_w, (float*)d_out);
}

// round 3
// speedup vs baseline: 1.2551x; 1.1902x over previous
#include <cuda_runtime.h>
#include <math.h>

// ---------------- problem constants ----------------
#define Bc   16
#define Tc   1536
#define Vc   64
#define F1c  16
#define Hc   4
#define FOc  8
#define F2c  32
#define K1c  32
#define K3c  16
#define NG   8
#define EMAX 512

// ---------------- device scratch ----------------
__device__ float d_weff[32 * 32];   // [k][ho]
__device__ float d_cvec[32];
__device__ float d_scale2[32], d_shift2[32], d_scale3[32], d_shift3[32];
__device__ int   d_off[Vc + 1];
__device__ int   d_srcs[EMAX];
__device__ float d_gbuf[Bc * Tc * F2c];

// ---------------- packed f32x2 helpers ----------------
typedef unsigned long long ull;
__device__ __forceinline__ ull pack2(float lo, float hi) {
    ull r;
    asm("mov.b64 %0, {%1, %2};" : "=l"(r) : "f"(lo), "f"(hi));
    return r;
}
__device__ __forceinline__ void fma2(ull& d, ull a, ull b) {
    asm("fma.rn.f32x2 %0, %1, %2, %0;" : "+l"(d) : "l"(a), "l"(b));
}
__device__ __forceinline__ void unpack2(ull v, float& lo, float& hi) {
    asm("mov.b64 {%0, %1}, %2;" : "=f"(lo), "=f"(hi) : "l"(v));
}

// ---------------- fast exp (|x| <= ~85), rel err ~3e-6 ----------------
__device__ __forceinline__ float fast_exp(float x) {
    x = fmaxf(fminf(x, 80.0f), -80.0f);
    float y = x * 1.4426950408889634f;
    float n = rintf(y);
    float f = y - n;
    float p = 1.3333558146428443e-3f;
    p = fmaf(p, f, 9.6181291076284772e-3f);
    p = fmaf(p, f, 5.5504108664821580e-2f);
    p = fmaf(p, f, 2.4022650695910071e-1f);
    p = fmaf(p, f, 6.9314718055994531e-1f);
    p = fmaf(p, f, 1.0f);
    int e = (int)n;
    return p * __int_as_float((e + 127) << 23);
}

// ---------------- setup ----------------
__global__ void setup_kernel(const float* __restrict__ conv1_w,
                             const float* __restrict__ bn1_g, const float* __restrict__ bn1_b,
                             const float* __restrict__ bn1_m, const float* __restrict__ bn1_v,
                             const float* __restrict__ gat_w,
                             const float* __restrict__ bn2_g, const float* __restrict__ bn2_b,
                             const float* __restrict__ bn2_m, const float* __restrict__ bn2_v,
                             const float* __restrict__ bn3_g, const float* __restrict__ bn3_b,
                             const float* __restrict__ bn3_m, const float* __restrict__ bn3_v,
                             const int* __restrict__ edge_index, int E) {
    __shared__ float sc1[F1c], sh1[F1c];
    __shared__ int scnt[Vc], soff[Vc + 1];
    __shared__ int sedge[2 * EMAX];
    int tid = threadIdx.x;
    // stage edge list in smem (kills the 36us serial-global-scan latency)
    for (int i = tid; i < 2 * E; i += blockDim.x) sedge[i] = edge_index[i];
    if (tid < F1c) {
        float s = bn1_g[tid] * rsqrtf(bn1_v[tid] + 1e-5f);
        sc1[tid] = s;
        sh1[tid] = bn1_b[tid] - bn1_m[tid] * s;
    }
    if (tid < F2c) {
        float s2 = bn2_g[tid] * rsqrtf(bn2_v[tid] + 1e-5f);
        d_scale2[tid] = s2; d_shift2[tid] = bn2_b[tid] - bn2_m[tid] * s2;
        float s3 = bn3_g[tid] * rsqrtf(bn3_v[tid] + 1e-5f);
        d_scale3[tid] = s3; d_shift3[tid] = bn3_b[tid] - bn3_m[tid] * s3;
    }
    __syncthreads();
    for (int i = tid; i < K1c * 32; i += blockDim.x) {
        int k = i >> 5, ho = i & 31;
        float s = 0.f;
        #pragma unroll
        for (int f = 0; f < F1c; f++)
            s = fmaf(gat_w[f * 32 + ho] * sc1[f], conv1_w[f * K1c + k], s);
        d_weff[i] = s;
    }
    if (tid < 32) {
        float s = 0.f;
        #pragma unroll
        for (int f = 0; f < F1c; f++) s = fmaf(gat_w[f * 32 + tid], sh1[f], s);
        d_cvec[tid] = s;
    }
    const int* src = sedge;
    const int* dst = sedge + E;
    if (tid < Vc) {
        int c = 0;
        for (int e = 0; e < E; e++) c += (dst[e] == tid);
        scnt[tid] = c;
    }
    __syncthreads();
    if (tid == 0) {
        int off = 0;
        for (int v = 0; v < Vc; v++) { soff[v] = off; off += scnt[v]; }
        soff[Vc] = off;
    }
    __syncthreads();
    if (tid <= Vc) d_off[tid] = soff[tid];
    if (tid < Vc) {
        int p = soff[tid];
        for (int e = 0; e < E; e++)
            if (dst[e] == tid) d_srcs[p++] = src[e];
    }
}

// ---------------- main ----------------
// smem floats: xs[2560] | wd0[1024] | wd1[1024] | cvec[32] asrc[32] adst[32] bias[32]
//              hbuf[16384] | es[2048] | ed[2048] | ints off[65] srcs[EMAX]
#define XS_F      (64 * 40)
#define SM_FLOATS (XS_F + 1024 + 1024 + 32 * 4 + NG * 2048 + NG * 256 * 2)
#define MAIN_SMEM (SM_FLOATS * 4 + (Vc + 1 + EMAX) * 4)

__global__ void __launch_bounds__(256, 2)
main_kernel(const float* __restrict__ x,
            const float* __restrict__ asrc_g,
            const float* __restrict__ adst_g,
            const float* __restrict__ bias_g,
            int E) {
    extern __shared__ float sm[];
    float* xs    = sm;
    float* wd0   = xs + XS_F;        // ull broadcast pairs {w[2kh],w[2kh]}  [kh][ho]
    float* wd1   = wd0 + 1024;       // {w[2kh+1],w[2kh+1]}
    float* cvec  = wd1 + 1024;
    float* sasrc = cvec + 32;
    float* sadst = sasrc + 32;
    float* sbias = sadst + 32;
    float* hbuf  = sbias + 32;       // [g][v][ho]
    float* es_s  = hbuf + NG * 2048;
    float* ed_s  = es_s + NG * 256;
    int*   soff  = (int*)(ed_s + NG * 256);
    int*   ssrc  = soff + (Vc + 1);

    const int tid = threadIdx.x;
    const int bx  = blockIdx.x;
    const int b   = bx / (Tc / NG);
    const int t0  = (bx % (Tc / NG)) * NG;

    // preamble: weights (duplicated pairs), tables, x slice
    for (int i = tid; i < 512; i += 256) {         // i = kh*32+ho
        int kh = i >> 5, ho = i & 31;
        float a = d_weff[(2 * kh) * 32 + ho];
        float c = d_weff[(2 * kh + 1) * 32 + ho];
        wd0[2 * i] = a; wd0[2 * i + 1] = a;
        wd1[2 * i] = c; wd1[2 * i + 1] = c;
    }
    if (tid < 32) {
        cvec[tid]  = d_cvec[tid];
        sasrc[tid] = asrc_g[tid];
        sadst[tid] = adst_g[tid];
        sbias[tid] = bias_g[tid];
    }
    for (int i = tid; i < Vc + 1; i += 256) soff[i] = d_off[i];
    for (int i = tid; i < E; i += 256) ssrc[i] = d_srcs[i];
    for (int idx = tid; idx < 64 * 40; idx += 256) {
        int v = idx / 40, j = idx - v * 40;
        int t = t0 - 15 + j;
        float val = 0.f;
        if (j < NG + 31 && t >= 0 && t < Tc) val = x[(b * Vc + v) * Tc + t];
        xs[idx] = val;
    }
    __syncthreads();

    // ---- conv via FFMA2, zero repacking:
    //  even k: acc2[p] (g=2p,2p+1) += w0 * pe[kh+p]
    //  odd  k: accO[q] (g=2q-1,2q) += w1 * pe[kh+q]   (lo of q=0 / hi of q=4 are dead)
    {
        const int ho = tid & 31;
        const int vslot = tid >> 5;
        const ull* wd0u = (const ull*)wd0;
        const ull* wd1u = (const ull*)wd1;
        const float cv = cvec[ho];
        const ull cvu = pack2(cv, cv);
        for (int i = 0; i < 8; i++) {
            const int v = vslot * 8 + i;
            const float* xr = xs + v * 40;
            ull pe[20];
            #pragma unroll
            for (int j = 0; j < 4; j++) pe[j] = *(const ull*)(xr + 2 * j);
            ull acc2[4], accO[5];
            #pragma unroll
            for (int p = 0; p < 4; p++) acc2[p] = cvu;
            #pragma unroll
            for (int q = 0; q < 5; q++) accO[q] = 0ULL;
            #pragma unroll
            for (int kh = 0; kh < 16; kh++) {
                pe[kh + 4] = *(const ull*)(xr + 2 * (kh + 4));
                const ull w0 = wd0u[kh * 32 + ho];
                const ull w1 = wd1u[kh * 32 + ho];
                #pragma unroll
                for (int p = 0; p < 4; p++) fma2(acc2[p], w0, pe[kh + p]);
                #pragma unroll
                for (int q = 0; q < 5; q++) fma2(accO[q], w1, pe[kh + q]);
            }
            float elo[4], ehi[4], olo[5], ohi[5];
            #pragma unroll
            for (int p = 0; p < 4; p++) unpack2(acc2[p], elo[p], ehi[p]);
            #pragma unroll
            for (int q = 0; q < 5; q++) unpack2(accO[q], olo[q], ohi[q]);
            #pragma unroll
            for (int p = 0; p < 4; p++) {
                hbuf[((2 * p)     * 64 + v) * 32 + ho] = elo[p] + ohi[p];
                hbuf[((2 * p + 1) * 64 + v) * 32 + ho] = ehi[p] + olo[p + 1];
            }
        }
    }
    __syncthreads();

    // ---- GAT: one warp per graph, single pass (no max-shift) ----
    {
        const int warp = tid >> 5, lane = tid & 31;
        float* h  = hbuf + warp * 2048;
        float* es = es_s + warp * 256;
        float* ed = ed_s + warp * 256;

        #pragma unroll
        for (int i = 0; i < 8; i++) {
            int p = lane + 32 * i;
            int head = p & 3, v = p >> 2;
            const float4* hv4 = (const float4*)(h + v * 32 + head * 8);
            const float4* as4 = (const float4*)(sasrc + head * 8);
            const float4* ad4 = (const float4*)(sadst + head * 8);
            float4 h0 = hv4[0], h1 = hv4[1];
            float4 a0 = as4[0], a1 = as4[1];
            float4 d0 = ad4[0], d1 = ad4[1];
            float se = h0.x * a0.x + h0.y * a0.y + h0.z * a0.z + h0.w * a0.w
                     + h1.x * a1.x + h1.y * a1.y + h1.z * a1.z + h1.w * a1.w;
            float sd = h0.x * d0.x + h0.y * d0.y + h0.z * d0.z + h0.w * d0.w
                     + h1.x * d1.x + h1.y * d1.y + h1.z * d1.z + h1.w * d1.w;
            es[p] = se; ed[p] = sd;
        }
        __syncwarp();

        float macc[8];
        #pragma unroll
        for (int o = 0; o < 8; o++) macc[o] = 0.f;
        const int head = lane & 3;
        for (int i = 0; i < 8; i++) {
            const int d = (lane >> 2) + 8 * i;
            const float edv = ed[d * 4 + head];
            const int beg = soff[d], end = soff[d + 1];
            float den = 0.f;
            float a0 = 0.f, a1 = 0.f, a2 = 0.f, a3 = 0.f;
            float a4 = 0.f, a5 = 0.f, a6 = 0.f, a7 = 0.f;
            for (int e = beg; e < end; e++) {
                int s = ssrc[e];
                float ev = es[s * 4 + head] + edv;
                ev = ev > 0.f ? ev : 0.2f * ev;
                float w = fast_exp(ev);
                den += w;
                const float4* hs4 = (const float4*)(h + s * 32 + head * 8);
                float4 q0 = hs4[0], q1 = hs4[1];
                a0 = fmaf(w, q0.x, a0); a1 = fmaf(w, q0.y, a1);
                a2 = fmaf(w, q0.z, a2); a3 = fmaf(w, q0.w, a3);
                a4 = fmaf(w, q1.x, a4); a5 = fmaf(w, q1.y, a5);
                a6 = fmaf(w, q1.z, a6); a7 = fmaf(w, q1.w, a7);
            }
            float inv = __frcp_rn(den);
            macc[0] = fmaf(a0, inv, macc[0]); macc[1] = fmaf(a1, inv, macc[1]);
            macc[2] = fmaf(a2, inv, macc[2]); macc[3] = fmaf(a3, inv, macc[3]);
            macc[4] = fmaf(a4, inv, macc[4]); macc[5] = fmaf(a5, inv, macc[5]);
            macc[6] = fmaf(a6, inv, macc[6]); macc[7] = fmaf(a7, inv, macc[7]);
        }
        #pragma unroll
        for (int o = 0; o < 8; o++) {
            macc[o] += __shfl_xor_sync(0xffffffffu, macc[o], 4);
            macc[o] += __shfl_xor_sync(0xffffffffu, macc[o], 8);
            macc[o] += __shfl_xor_sync(0xffffffffu, macc[o], 16);
        }
        if (lane < 4) {
            const int t = t0 + warp;
            float* gout = d_gbuf + (b * Tc + t) * 32 + head * 8;
            #pragma unroll
            for (int o = 0; o < 8; o++)
                gout[o] = macc[o] * (1.0f / 64.0f) + sbias[head * 8 + o];
        }
    }
}

// ---------------- tail ----------------
#define TP 192
#define TAIL_SMEM ((F2c * F2c * K3c + F2c * 40 + F2c * 24) * 4)

__global__ void __launch_bounds__(256)
tail_kernel(const float* __restrict__ conv3_w, float* __restrict__ out) {
    extern __shared__ float sm[];
    float* w3s   = sm;
    float* ptile = w3s + F2c * F2c * K3c;
    float* ytile = ptile + F2c * 40;

    const int tid = threadIdx.x;
    const int b = blockIdx.x;
    const int tile = blockIdx.y;
    const int tc0 = tile * 24;

    for (int i = tid; i < F2c * F2c * K3c; i += 256) w3s[i] = conv3_w[i];
    for (int i = tid; i < F2c * 40; i += 256) {
        int fi = i & 31, j = i >> 5;
        int tc = tc0 - 7 + j;
        float val = 0.f;
        if (j < 39 && tc >= 0 && tc < TP) {
            float scv = d_scale2[fi], shv = d_shift2[fi];
            float s = 0.f;
            #pragma unroll
            for (int r = 0; r < 8; r++) {
                float gv = fmaf(scv, d_gbuf[(b * Tc + tc * 8 + r) * 32 + fi], shv);
                s += gv > 0.f ? gv : (__expf(gv) - 1.f);
            }
            val = s * 0.125f;
        }
        ptile[fi * 40 + j] = val;
    }
    __syncthreads();

    for (int oidx = tid; oidx < F2c * 24; oidx += 256) {
        int fo = oidx / 24;
        int tcl = oidx - fo * 24;
        float acc = 0.f;
        for (int fi = 0; fi < F2c; fi++) {
            const float* wr = w3s + (fo * 32 + fi) * 16;
            const float* pr = ptile + fi * 40 + tcl;
            #pragma unroll
            for (int k = 0; k < K3c; k++) acc = fmaf(wr[k], pr[k], acc);
        }
        float z = fmaf(d_scale3[fo], acc, d_shift3[fo]);
        z = z > 0.f ? z : (__expf(z) - 1.f);
        ytile[fo * 24 + tcl] = z;
    }
    __syncthreads();

    for (int i = tid; i < F2c * 6; i += 256) {
        int fo = i / 6, tl = i - fo * 6;
        const float* yr = ytile + fo * 24 + tl * 4;
        float s = 0.25f * (yr[0] + yr[1] + yr[2] + yr[3]);
        out[(b * 32 + fo) * 48 + tile * 6 + tl] = s;
    }
}

// ---------------- launch ----------------
extern "C" void kernel_launch(void* const* d_in, const int* in_sizes, int n_in,
                              void* d_out, int out_size) {
    const float* x        = (const float*)d_in[0];
    const float* conv1_w  = (const float*)d_in[1];
    const float* bn1_g    = (const float*)d_in[2];
    const float* bn1_b    = (const float*)d_in[3];
    const float* bn1_m    = (const float*)d_in[4];
    const float* bn1_v    = (const float*)d_in[5];
    const float* gat_w    = (const float*)d_in[6];
    const float* gat_asrc = (const float*)d_in[7];
    const float* gat_adst = (const float*)d_in[8];
    const float* gat_bias = (const float*)d_in[9];
    const float* bn2_g    = (const float*)d_in[10];
    const float* bn2_b    = (const float*)d_in[11];
    const float* bn2_m    = (const float*)d_in[12];
    const float* bn2_v    = (const float*)d_in[13];
    const float* conv3_w  = (const float*)d_in[14];
    const float* bn3_g    = (const float*)d_in[15];
    const float* bn3_b    = (const float*)d_in[16];
    const float* bn3_m    = (const float*)d_in[17];
    const float* bn3_v    = (const float*)d_in[18];
    const int*   edge_idx = (const int*)d_in[19];
    int E = in_sizes[19] / 2;
    if (E > EMAX) E = EMAX;

    cudaFuncSetAttribute(main_kernel, cudaFuncAttributeMaxDynamicSharedMemorySize, MAIN_SMEM);
    cudaFuncSetAttribute(tail_kernel, cudaFuncAttributeMaxDynamicSharedMemorySize, TAIL_SMEM);

    setup_kernel<<<1, 256>>>(conv1_w, bn1_g, bn1_b, bn1_m, bn1_v, gat_w,
                             bn2_g, bn2_b, bn2_m, bn2_v,
                             bn3_g, bn3_b, bn3_m, bn3_v, edge_idx, E);
    main_kernel<<<Bc * (Tc / NG), 256, MAIN_SMEM>>>(x, gat_asrc, gat_adst, gat_bias, E);
    tail_kernel<<<dim3(Bc, 8), 256, TAIL_SMEM>>>(conv3_w, (float*)d_out);
}

// round 4
// speedup vs baseline: 1.3505x; 1.0760x over previous
#include <cuda_runtime.h>
#include <math.h>

// ---------------- problem constants ----------------
#define Bc   16
#define Tc   1536
#define Vc   64
#define F1c  16
#define Hc   4
#define FOc  8
#define F2c  32
#define K1c  32
#define K3c  16
#define NG   8
#define EMAX 512

// ---------------- device scratch ----------------
__device__ float d_weff[32 * 32];   // [k][ho]
__device__ float d_cvec[32];
__device__ float d_scale2[32], d_shift2[32], d_scale3[32], d_shift3[32];
__device__ int   d_off[Vc + 1];
__device__ int   d_srcs[EMAX];
__device__ float d_gbuf[Bc * Tc * F2c];

// ---------------- packed f32x2 helpers ----------------
typedef unsigned long long ull;
__device__ __forceinline__ ull pack2(float lo, float hi) {
    ull r;
    asm("mov.b64 %0, {%1, %2};" : "=l"(r) : "f"(lo), "f"(hi));
    return r;
}
__device__ __forceinline__ void fma2(ull& d, ull a, ull b) {
    asm("fma.rn.f32x2 %0, %1, %2, %0;" : "+l"(d) : "l"(a), "l"(b));
}
__device__ __forceinline__ void unpack2(ull v, float& lo, float& hi) {
    asm("mov.b64 {%0, %1}, %2;" : "=f"(lo), "=f"(hi) : "l"(v));
}

// ---------------- setup ----------------
__global__ void setup_kernel(const float* __restrict__ conv1_w,
                             const float* __restrict__ bn1_g, const float* __restrict__ bn1_b,
                             const float* __restrict__ bn1_m, const float* __restrict__ bn1_v,
                             const float* __restrict__ gat_w,
                             const float* __restrict__ bn2_g, const float* __restrict__ bn2_b,
                             const float* __restrict__ bn2_m, const float* __restrict__ bn2_v,
                             const float* __restrict__ bn3_g, const float* __restrict__ bn3_b,
                             const float* __restrict__ bn3_m, const float* __restrict__ bn3_v,
                             const int* __restrict__ edge_index, int E) {
    __shared__ float sc1[F1c], sh1[F1c];
    __shared__ float s_c1[F1c * K1c];      // conv1 weights staged
    __shared__ float s_gw[F1c * 32];       // gat W staged
    __shared__ int sedge[2 * EMAX];
    __shared__ int cnt4[Vc][4];
    __shared__ int soff[Vc + 1];
    int tid = threadIdx.x;

    for (int i = tid; i < 2 * E; i += blockDim.x) sedge[i] = edge_index[i];
    for (int i = tid; i < F1c * K1c; i += blockDim.x) s_c1[i] = conv1_w[i];
    for (int i = tid; i < F1c * 32; i += blockDim.x) s_gw[i] = gat_w[i];
    if (tid < F1c) {
        float s = bn1_g[tid] * rsqrtf(bn1_v[tid] + 1e-5f);
        sc1[tid] = s;
        sh1[tid] = bn1_b[tid] - bn1_m[tid] * s;
    }
    if (tid < F2c) {
        float s2 = bn2_g[tid] * rsqrtf(bn2_v[tid] + 1e-5f);
        d_scale2[tid] = s2; d_shift2[tid] = bn2_b[tid] - bn2_m[tid] * s2;
        float s3 = bn3_g[tid] * rsqrtf(bn3_v[tid] + 1e-5f);
        d_scale3[tid] = s3; d_shift3[tid] = bn3_b[tid] - bn3_m[tid] * s3;
    }
    __syncthreads();
    for (int i = tid; i < K1c * 32; i += blockDim.x) {
        int k = i >> 5, ho = i & 31;
        float s = 0.f;
        #pragma unroll
        for (int f = 0; f < F1c; f++)
            s = fmaf(s_gw[f * 32 + ho] * sc1[f], s_c1[f * K1c + k], s);
        d_weff[i] = s;
    }
    if (tid < 32) {
        float s = 0.f;
        #pragma unroll
        for (int f = 0; f < F1c; f++) s = fmaf(s_gw[f * 32 + tid], sh1[f], s);
        d_cvec[tid] = s;
    }
    // deterministic CSR, 4 threads per dst scanning disjoint quarters
    const int* src = sedge;
    const int* dst = sedge + E;
    const int qsz = (E + 3) >> 2;
    const int v = tid >> 2, q = tid & 3;
    const int lo = q * qsz;
    const int hi = min(E, lo + qsz);
    {
        int c = 0;
        for (int e = lo; e < hi; e++) c += (dst[e] == v);
        cnt4[v][q] = c;
    }
    __syncthreads();
    if (tid == 0) {
        int off = 0;
        for (int vv = 0; vv < Vc; vv++) {
            soff[vv] = off;
            off += cnt4[vv][0] + cnt4[vv][1] + cnt4[vv][2] + cnt4[vv][3];
        }
        soff[Vc] = off;
    }
    __syncthreads();
    if (tid <= Vc) d_off[tid] = soff[tid];
    {
        int p = soff[v];
        for (int qq = 0; qq < 4; qq++) if (qq < q) p += cnt4[v][qq];
        for (int e = lo; e < hi; e++)
            if (dst[e] == v) d_srcs[p++] = src[e];
    }
}

// ---------------- main ----------------
// smem floats: xs[2560] | asrc[32] adst[32] bias[32] | hbuf[16384] | es[2048] ed[2048]
//              ints: off[65] srcs[512]
#define XS_F      (64 * 40)
#define SM_FLOATS (XS_F + 96 + NG * 2048 + NG * 256 * 2)
#define MAIN_SMEM (SM_FLOATS * 4 + (Vc + 1 + EMAX) * 4)

__global__ void __launch_bounds__(256, 2)
main_kernel(const float* __restrict__ x,
            const float* __restrict__ asrc_g,
            const float* __restrict__ adst_g,
            const float* __restrict__ bias_g,
            int E) {
    extern __shared__ float sm[];
    float* xs    = sm;
    float* sasrc = xs + XS_F;
    float* sadst = sasrc + 32;
    float* sbias = sadst + 32;
    float* hbuf  = sbias + 32;       // [g][v][ho]
    float* es_s  = hbuf + NG * 2048;
    float* ed_s  = es_s + NG * 256;
    int*   soff  = (int*)(ed_s + NG * 256);
    int*   ssrc  = soff + (Vc + 1);

    const int tid = threadIdx.x;
    const int bx  = blockIdx.x;
    const int b   = bx / (Tc / NG);
    const int t0  = (bx % (Tc / NG)) * NG;

    if (tid < 32) {
        sasrc[tid] = asrc_g[tid];
        sadst[tid] = adst_g[tid];
        sbias[tid] = bias_g[tid];
    }
    for (int i = tid; i < Vc + 1; i += 256) soff[i] = d_off[i];
    for (int i = tid; i < E; i += 256) ssrc[i] = d_srcs[i];
    for (int idx = tid; idx < 64 * 40; idx += 256) {
        int v = idx / 40, j = idx - v * 40;
        int t = t0 - 15 + j;
        float val = 0.f;
        if (j < NG + 31 && t >= 0 && t < Tc) val = x[(b * Vc + v) * Tc + t];
        xs[idx] = val;
    }
    __syncthreads();

    // ---- conv via FFMA2, weights in registers (x loads are smem broadcasts) ----
    {
        const int ho = tid & 31;
        const int vslot = tid >> 5;
        float w[K1c];
        #pragma unroll
        for (int k = 0; k < K1c; k++) w[k] = d_weff[k * 32 + ho];   // coalesced, L1/L2-hot
        const float cv = d_cvec[ho];
        const ull cvu = pack2(cv, cv);
        for (int i = 0; i < 8; i++) {
            const int v = vslot * 8 + i;
            const float* xr = xs + v * 40;
            ull pe[20];
            #pragma unroll
            for (int j = 0; j < 4; j++) pe[j] = *(const ull*)(xr + 2 * j);
            ull acc2[4], accO[5];
            #pragma unroll
            for (int p = 0; p < 4; p++) acc2[p] = cvu;
            #pragma unroll
            for (int q = 0; q < 5; q++) accO[q] = 0ULL;
            #pragma unroll
            for (int kh = 0; kh < 16; kh++) {
                pe[kh + 4] = *(const ull*)(xr + 2 * (kh + 4));
                const ull w0 = pack2(w[2 * kh],     w[2 * kh]);
                const ull w1 = pack2(w[2 * kh + 1], w[2 * kh + 1]);
                #pragma unroll
                for (int p = 0; p < 4; p++) fma2(acc2[p], w0, pe[kh + p]);
                #pragma unroll
                for (int q = 0; q < 5; q++) fma2(accO[q], w1, pe[kh + q]);
            }
            float elo[4], ehi[4], olo[5], ohi[5];
            #pragma unroll
            for (int p = 0; p < 4; p++) unpack2(acc2[p], elo[p], ehi[p]);
            #pragma unroll
            for (int q = 0; q < 5; q++) unpack2(accO[q], olo[q], ohi[q]);
            #pragma unroll
            for (int p = 0; p < 4; p++) {
                hbuf[((2 * p)     * 64 + v) * 32 + ho] = elo[p] + ohi[p];
                hbuf[((2 * p + 1) * 64 + v) * 32 + ho] = ehi[p] + olo[p + 1];
            }
        }
    }
    __syncthreads();

    // ---- GAT: one warp per graph, single pass, MUFU exp ----
    {
        const int warp = tid >> 5, lane = tid & 31;
        float* h  = hbuf + warp * 2048;
        float* es = es_s + warp * 256;
        float* ed = ed_s + warp * 256;

        #pragma unroll
        for (int i = 0; i < 8; i++) {
            int p = lane + 32 * i;
            int head = p & 3, v = p >> 2;
            const float4* hv4 = (const float4*)(h + v * 32 + head * 8);
            const float4* as4 = (const float4*)(sasrc + head * 8);
            const float4* ad4 = (const float4*)(sadst + head * 8);
            float4 h0 = hv4[0], h1 = hv4[1];
            float4 a0 = as4[0], a1 = as4[1];
            float4 d0 = ad4[0], d1 = ad4[1];
            float se = h0.x * a0.x + h0.y * a0.y + h0.z * a0.z + h0.w * a0.w
                     + h1.x * a1.x + h1.y * a1.y + h1.z * a1.z + h1.w * a1.w;
            float sd = h0.x * d0.x + h0.y * d0.y + h0.z * d0.z + h0.w * d0.w
                     + h1.x * d1.x + h1.y * d1.y + h1.z * d1.z + h1.w * d1.w;
            es[p] = se; ed[p] = sd;
        }
        __syncwarp();

        float macc[8];
        #pragma unroll
        for (int o = 0; o < 8; o++) macc[o] = 0.f;
        const int head = lane & 3;
        for (int i = 0; i < 8; i++) {
            const int d = (lane >> 2) + 8 * i;
            const float edv = ed[d * 4 + head];
            const int beg = soff[d], end = soff[d + 1];
            float den = 0.f;
            float a0 = 0.f, a1 = 0.f, a2 = 0.f, a3 = 0.f;
            float a4 = 0.f, a5 = 0.f, a6 = 0.f, a7 = 0.f;
            for (int e = beg; e < end; e++) {
                int s = ssrc[e];
                float ev = es[s * 4 + head] + edv;
                ev = ev > 0.f ? ev : 0.2f * ev;
                float wexp = __expf(ev);          // MUFU.EX2 path
                den += wexp;
                const float4* hs4 = (const float4*)(h + s * 32 + head * 8);
                float4 q0 = hs4[0], q1 = hs4[1];
                a0 = fmaf(wexp, q0.x, a0); a1 = fmaf(wexp, q0.y, a1);
                a2 = fmaf(wexp, q0.z, a2); a3 = fmaf(wexp, q0.w, a3);
                a4 = fmaf(wexp, q1.x, a4); a5 = fmaf(wexp, q1.y, a5);
                a6 = fmaf(wexp, q1.z, a6); a7 = fmaf(wexp, q1.w, a7);
            }
            float inv = __frcp_rn(den);
            macc[0] = fmaf(a0, inv, macc[0]); macc[1] = fmaf(a1, inv, macc[1]);
            macc[2] = fmaf(a2, inv, macc[2]); macc[3] = fmaf(a3, inv, macc[3]);
            macc[4] = fmaf(a4, inv, macc[4]); macc[5] = fmaf(a5, inv, macc[5]);
            macc[6] = fmaf(a6, inv, macc[6]); macc[7] = fmaf(a7, inv, macc[7]);
        }
        #pragma unroll
        for (int o = 0; o < 8; o++) {
            macc[o] += __shfl_xor_sync(0xffffffffu, macc[o], 4);
            macc[o] += __shfl_xor_sync(0xffffffffu, macc[o], 8);
            macc[o] += __shfl_xor_sync(0xffffffffu, macc[o], 16);
        }
        if (lane < 4) {
            const int t = t0 + warp;
            float* gout = d_gbuf + (b * Tc + t) * 32 + head * 8;
            #pragma unroll
            for (int o = 0; o < 8; o++)
                gout[o] = macc[o] * (1.0f / 64.0f) + sbias[head * 8 + o];
        }
    }
}

// ---------------- tail ----------------
#define TP 192
#define TAIL_SMEM ((F2c * F2c * K3c + F2c * 40 + F2c * 24) * 4)

__global__ void __launch_bounds__(256)
tail_kernel(const float* __restrict__ conv3_w, float* __restrict__ out) {
    extern __shared__ float sm[];
    float* w3s   = sm;
    float* ptile = w3s + F2c * F2c * K3c;
    float* ytile = ptile + F2c * 40;

    const int tid = threadIdx.x;
    const int b = blockIdx.x;
    const int tile = blockIdx.y;
    const int tc0 = tile * 24;

    for (int i = tid; i < F2c * F2c * K3c; i += 256) w3s[i] = conv3_w[i];
    for (int i = tid; i < F2c * 40; i += 256) {
        int fi = i & 31, j = i >> 5;
        int tc = tc0 - 7 + j;
        float val = 0.f;
        if (j < 39 && tc >= 0 && tc < TP) {
            float scv = d_scale2[fi], shv = d_shift2[fi];
            float s = 0.f;
            #pragma unroll
            for (int r = 0; r < 8; r++) {
                float gv = fmaf(scv, d_gbuf[(b * Tc + tc * 8 + r) * 32 + fi], shv);
                s += gv > 0.f ? gv : (__expf(gv) - 1.f);
            }
            val = s * 0.125f;
        }
        ptile[fi * 40 + j] = val;
    }
    __syncthreads();

    for (int oidx = tid; oidx < F2c * 24; oidx += 256) {
        int fo = oidx / 24;
        int tcl = oidx - fo * 24;
        float acc = 0.f;
        for (int fi = 0; fi < F2c; fi++) {
            const float* wr = w3s + (fo * 32 + fi) * 16;
            const float* pr = ptile + fi * 40 + tcl;
            #pragma unroll
            for (int k = 0; k < K3c; k++) acc = fmaf(wr[k], pr[k], acc);
        }
        float z = fmaf(d_scale3[fo], acc, d_shift3[fo]);
        z = z > 0.f ? z : (__expf(z) - 1.f);
        ytile[fo * 24 + tcl] = z;
    }
    __syncthreads();

    for (int i = tid; i < F2c * 6; i += 256) {
        int fo = i / 6, tl = i - fo * 6;
        const float* yr = ytile + fo * 24 + tl * 4;
        float s = 0.25f * (yr[0] + yr[1] + yr[2] + yr[3]);
        out[(b * 32 + fo) * 48 + tile * 6 + tl] = s;
    }
}

// ---------------- launch ----------------
extern "C" void kernel_launch(void* const* d_in, const int* in_sizes, int n_in,
                              void* d_out, int out_size) {
    const float* x        = (const float*)d_in[0];
    const float* conv1_w  = (const float*)d_in[1];
    const float* bn1_g    = (const float*)d_in[2];
    const float* bn1_b    = (const float*)d_in[3];
    const float* bn1_m    = (const float*)d_in[4];
    const float* bn1_v    = (const float*)d_in[5];
    const float* gat_w    = (const float*)d_in[6];
    const float* gat_asrc = (const float*)d_in[7];
    const float* gat_adst = (const float*)d_in[8];
    const float* gat_bias = (const float*)d_in[9];
    const float* bn2_g    = (const float*)d_in[10];
    const float* bn2_b    = (const float*)d_in[11];
    const float* bn2_m    = (const float*)d_in[12];
    const float* bn2_v    = (const float*)d_in[13];
    const float* conv3_w  = (const float*)d_in[14];
    const float* bn3_g    = (const float*)d_in[15];
    const float* bn3_b    = (const float*)d_in[16];
    const float* bn3_m    = (const float*)d_in[17];
    const float* bn3_v    = (const float*)d_in[18];
    const int*   edge_idx = (const int*)d_in[19];
    int E = in_sizes[19] / 2;
    if (E > EMAX) E = EMAX;

    cudaFuncSetAttribute(main_kernel, cudaFuncAttributeMaxDynamicSharedMemorySize, MAIN_SMEM);
    cudaFuncSetAttribute(tail_kernel, cudaFuncAttributeMaxDynamicSharedMemorySize, TAIL_SMEM);

    setup_kernel<<<1, 256>>>(conv1_w, bn1_g, bn1_b, bn1_m, bn1_v, gat_w,
                             bn2_g, bn2_b, bn2_m, bn2_v,
                             bn3_g, bn3_b, bn3_m, bn3_v, edge_idx, E);
    main_kernel<<<Bc * (Tc / NG), 256, MAIN_SMEM>>>(x, gat_asrc, gat_adst, gat_bias, E);
    tail_kernel<<<dim3(Bc, 8), 256, TAIL_SMEM>>>(conv3_w, (float*)d_out);
}

// round 5
// speedup vs baseline: 1.3744x; 1.0177x over previous
#include <cuda_runtime.h>
#include <math.h>

// ---------------- problem constants ----------------
#define Bc   16
#define Tc   1536
#define Vc   64
#define F1c  16
#define Hc   4
#define FOc  8
#define F2c  32
#define K1c  32
#define K3c  16
#define NG   8
#define EMAX 512

// hbuf row stride (floats): 36 = conflict-free float4 GAT reads, 16B aligned
#define HSTR 36
#define HG   (Vc * HSTR)     // 2304 floats per graph
// es transposed layout stride
#define ESTR 68
#define ESG  (Hc * ESTR)     // 272 floats per graph

// ---------------- device scratch ----------------
__device__ float d_weff[32 * 32];   // [k][ho]
__device__ float d_cvec[32];
__device__ float d_scale2[32], d_shift2[32], d_scale3[32], d_shift3[32];
__device__ int   d_off[Vc + 1];
__device__ int   d_srcs[EMAX];
__device__ float d_gbuf[Bc * Tc * F2c];

// ---------------- packed f32x2 helpers ----------------
typedef unsigned long long ull;
__device__ __forceinline__ ull pack2(float lo, float hi) {
    ull r;
    asm("mov.b64 %0, {%1, %2};" : "=l"(r) : "f"(lo), "f"(hi));
    return r;
}
__device__ __forceinline__ void fma2(ull& d, ull a, ull b) {
    asm("fma.rn.f32x2 %0, %1, %2, %0;" : "+l"(d) : "l"(a), "l"(b));
}
__device__ __forceinline__ void unpack2(ull v, float& lo, float& hi) {
    asm("mov.b64 {%0, %1}, %2;" : "=f"(lo), "=f"(hi) : "l"(v));
}

// ---------------- setup ----------------
__global__ void setup_kernel(const float* __restrict__ conv1_w,
                             const float* __restrict__ bn1_g, const float* __restrict__ bn1_b,
                             const float* __restrict__ bn1_m, const float* __restrict__ bn1_v,
                             const float* __restrict__ gat_w,
                             const float* __restrict__ bn2_g, const float* __restrict__ bn2_b,
                             const float* __restrict__ bn2_m, const float* __restrict__ bn2_v,
                             const float* __restrict__ bn3_g, const float* __restrict__ bn3_b,
                             const float* __restrict__ bn3_m, const float* __restrict__ bn3_v,
                             const int* __restrict__ edge_index, int E) {
    __shared__ float sc1[F1c], sh1[F1c];
    __shared__ float s_c1[F1c * K1c];
    __shared__ float s_gw[F1c * 32];
    __shared__ int sedge[2 * EMAX];
    __shared__ int cnt4[Vc][4];
    __shared__ int soff[Vc + 1];
    int tid = threadIdx.x;

    for (int i = tid; i < 2 * E; i += blockDim.x) sedge[i] = edge_index[i];
    for (int i = tid; i < F1c * K1c; i += blockDim.x) s_c1[i] = conv1_w[i];
    for (int i = tid; i < F1c * 32; i += blockDim.x) s_gw[i] = gat_w[i];
    if (tid < F1c) {
        float s = bn1_g[tid] * rsqrtf(bn1_v[tid] + 1e-5f);
        sc1[tid] = s;
        sh1[tid] = bn1_b[tid] - bn1_m[tid] * s;
    }
    if (tid < F2c) {
        float s2 = bn2_g[tid] * rsqrtf(bn2_v[tid] + 1e-5f);
        d_scale2[tid] = s2; d_shift2[tid] = bn2_b[tid] - bn2_m[tid] * s2;
        float s3 = bn3_g[tid] * rsqrtf(bn3_v[tid] + 1e-5f);
        d_scale3[tid] = s3; d_shift3[tid] = bn3_b[tid] - bn3_m[tid] * s3;
    }
    __syncthreads();
    for (int i = tid; i < K1c * 32; i += blockDim.x) {
        int k = i >> 5, ho = i & 31;
        float s = 0.f;
        #pragma unroll
        for (int f = 0; f < F1c; f++)
            s = fmaf(s_gw[f * 32 + ho] * sc1[f], s_c1[f * K1c + k], s);
        d_weff[i] = s;
    }
    if (tid < 32) {
        float s = 0.f;
        #pragma unroll
        for (int f = 0; f < F1c; f++) s = fmaf(s_gw[f * 32 + tid], sh1[f], s);
        d_cvec[tid] = s;
    }
    const int* src = sedge;
    const int* dst = sedge + E;
    const int qsz = (E + 3) >> 2;
    const int v = tid >> 2, q = tid & 3;
    const int lo = q * qsz;
    const int hi = min(E, lo + qsz);
    {
        int c = 0;
        for (int e = lo; e < hi; e++) c += (dst[e] == v);
        cnt4[v][q] = c;
    }
    __syncthreads();
    if (tid == 0) {
        int off = 0;
        for (int vv = 0; vv < Vc; vv++) {
            soff[vv] = off;
            off += cnt4[vv][0] + cnt4[vv][1] + cnt4[vv][2] + cnt4[vv][3];
        }
        soff[Vc] = off;
    }
    __syncthreads();
    if (tid <= Vc) d_off[tid] = soff[tid];
    {
        int p = soff[v];
        for (int qq = 0; qq < 4; qq++) if (qq < q) p += cnt4[v][qq];
        for (int e = lo; e < hi; e++)
            if (dst[e] == v) d_srcs[p++] = src[e];
    }
}

// ---------------- main ----------------
// smem floats: xs[2560] | asrc[32] adst[32] bias[32] | hbuf[8*2304] | es[8*272] ed[8*256]
//              ints: off[65] srcs[512]
#define XS_F      (64 * 40)
#define SM_FLOATS (XS_F + 96 + NG * HG + NG * ESG + NG * 256)
#define MAIN_SMEM (SM_FLOATS * 4 + (Vc + 1 + EMAX) * 4)

__global__ void __launch_bounds__(256, 2)
main_kernel(const float* __restrict__ x,
            const float* __restrict__ asrc_g,
            const float* __restrict__ adst_g,
            const float* __restrict__ bias_g,
            int E) {
    extern __shared__ float sm[];
    float* xs    = sm;
    float* sasrc = xs + XS_F;
    float* sadst = sasrc + 32;
    float* sbias = sadst + 32;
    float* hbuf  = sbias + 32;            // [g][v][HSTR]
    float* es_s  = hbuf + NG * HG;        // [g][head][ESTR]
    float* ed_s  = es_s + NG * ESG;       // [g][v*4+head]
    int*   soff  = (int*)(ed_s + NG * 256);
    int*   ssrc  = soff + (Vc + 1);

    const int tid = threadIdx.x;
    const int bx  = blockIdx.x;
    const int b   = bx / (Tc / NG);
    const int t0  = (bx % (Tc / NG)) * NG;

    if (tid < 32) {
        sasrc[tid] = asrc_g[tid];
        sadst[tid] = adst_g[tid];
        sbias[tid] = bias_g[tid];
    }
    for (int i = tid; i < Vc + 1; i += 256) soff[i] = d_off[i];
    for (int i = tid; i < E; i += 256) ssrc[i] = d_srcs[i];
    for (int idx = tid; idx < 64 * 40; idx += 256) {
        int v = idx / 40, j = idx - v * 40;
        int t = t0 - 15 + j;
        float val = 0.f;
        if (j < NG + 31 && t >= 0 && t < Tc) val = x[(b * Vc + v) * Tc + t];
        xs[idx] = val;
    }
    __syncthreads();

    // ---- conv via FFMA2, weights in registers ----
    {
        const int ho = tid & 31;
        const int vslot = tid >> 5;
        float w[K1c];
        #pragma unroll
        for (int k = 0; k < K1c; k++) w[k] = d_weff[k * 32 + ho];
        const float cv = d_cvec[ho];
        const ull cvu = pack2(cv, cv);
        for (int i = 0; i < 8; i++) {
            const int v = vslot * 8 + i;
            const float* xr = xs + v * 40;
            ull pe[20];
            #pragma unroll
            for (int j = 0; j < 4; j++) pe[j] = *(const ull*)(xr + 2 * j);
            ull acc2[4], accO[5];
            #pragma unroll
            for (int p = 0; p < 4; p++) acc2[p] = cvu;
            #pragma unroll
            for (int q = 0; q < 5; q++) accO[q] = 0ULL;
            #pragma unroll
            for (int kh = 0; kh < 16; kh++) {
                pe[kh + 4] = *(const ull*)(xr + 2 * (kh + 4));
                const ull w0 = pack2(w[2 * kh],     w[2 * kh]);
                const ull w1 = pack2(w[2 * kh + 1], w[2 * kh + 1]);
                #pragma unroll
                for (int p = 0; p < 4; p++) fma2(acc2[p], w0, pe[kh + p]);
                #pragma unroll
                for (int q = 0; q < 5; q++) fma2(accO[q], w1, pe[kh + q]);
            }
            float elo[4], ehi[4], olo[5], ohi[5];
            #pragma unroll
            for (int p = 0; p < 4; p++) unpack2(acc2[p], elo[p], ehi[p]);
            #pragma unroll
            for (int q = 0; q < 5; q++) unpack2(accO[q], olo[q], ohi[q]);
            #pragma unroll
            for (int p = 0; p < 4; p++) {
                hbuf[(2 * p)     * HG + v * HSTR + ho] = elo[p] + ohi[p];
                hbuf[(2 * p + 1) * HG + v * HSTR + ho] = ehi[p] + olo[p + 1];
            }
        }
    }
    __syncthreads();

    // ---- GAT: one warp per graph, single pass, MUFU exp ----
    {
        const int warp = tid >> 5, lane = tid & 31;
        float* h  = hbuf + warp * HG;
        float* es = es_s + warp * ESG;      // [head][ESTR]
        float* ed = ed_s + warp * 256;      // [v*4+head]

        #pragma unroll
        for (int i = 0; i < 8; i++) {
            int p = lane + 32 * i;
            int head = p & 3, v = p >> 2;
            const float4* hv4 = (const float4*)(h + v * HSTR + head * 8);
            const float4* as4 = (const float4*)(sasrc + head * 8);
            const float4* ad4 = (const float4*)(sadst + head * 8);
            float4 h0 = hv4[0], h1 = hv4[1];
            float4 a0 = as4[0], a1 = as4[1];
            float4 d0 = ad4[0], d1 = ad4[1];
            float se = h0.x * a0.x + h0.y * a0.y + h0.z * a0.z + h0.w * a0.w
                     + h1.x * a1.x + h1.y * a1.y + h1.z * a1.z + h1.w * a1.w;
            float sd = h0.x * d0.x + h0.y * d0.y + h0.z * d0.z + h0.w * d0.w
                     + h1.x * d1.x + h1.y * d1.y + h1.z * d1.z + h1.w * d1.w;
            es[head * ESTR + v] = se;
            ed[v * 4 + head]    = sd;
        }
        __syncwarp();

        float macc[8];
        #pragma unroll
        for (int o = 0; o < 8; o++) macc[o] = 0.f;
        const int head = lane & 3;
        const float* esb = es + head * ESTR;
        for (int i = 0; i < 8; i++) {
            const int d = (lane >> 2) + 8 * i;
            const float edv = ed[d * 4 + head];
            const int beg = soff[d], end = soff[d + 1];
            float den = 0.f;
            float a0 = 0.f, a1 = 0.f, a2 = 0.f, a3 = 0.f;
            float a4 = 0.f, a5 = 0.f, a6 = 0.f, a7 = 0.f;
            for (int e = beg; e < end; e++) {
                int s = ssrc[e];
                float ev = esb[s] + edv;
                ev = ev > 0.f ? ev : 0.2f * ev;
                float wexp = __expf(ev);
                den += wexp;
                const float4* hs4 = (const float4*)(h + s * HSTR + head * 8);
                float4 q0 = hs4[0], q1 = hs4[1];
                a0 = fmaf(wexp, q0.x, a0); a1 = fmaf(wexp, q0.y, a1);
                a2 = fmaf(wexp, q0.z, a2); a3 = fmaf(wexp, q0.w, a3);
                a4 = fmaf(wexp, q1.x, a4); a5 = fmaf(wexp, q1.y, a5);
                a6 = fmaf(wexp, q1.z, a6); a7 = fmaf(wexp, q1.w, a7);
            }
            float inv = __frcp_rn(den);
            macc[0] = fmaf(a0, inv, macc[0]); macc[1] = fmaf(a1, inv, macc[1]);
            macc[2] = fmaf(a2, inv, macc[2]); macc[3] = fmaf(a3, inv, macc[3]);
            macc[4] = fmaf(a4, inv, macc[4]); macc[5] = fmaf(a5, inv, macc[5]);
            macc[6] = fmaf(a6, inv, macc[6]); macc[7] = fmaf(a7, inv, macc[7]);
        }
        #pragma unroll
        for (int o = 0; o < 8; o++) {
            macc[o] += __shfl_xor_sync(0xffffffffu, macc[o], 4);
            macc[o] += __shfl_xor_sync(0xffffffffu, macc[o], 8);
            macc[o] += __shfl_xor_sync(0xffffffffu, macc[o], 16);
        }
        if (lane < 4) {
            const int t = t0 + warp;
            float* gout = d_gbuf + (b * Tc + t) * 32 + head * 8;
            #pragma unroll
            for (int o = 0; o < 8; o++)
                gout[o] = macc[o] * (1.0f / 64.0f) + sbias[head * 8 + o];
        }
    }
}

// ---------------- tail ----------------
#define TP 192
#define TAIL_SMEM ((F2c * F2c * K3c + F2c * 40 + F2c * 24) * 4)

__global__ void __launch_bounds__(256)
tail_kernel(const float* __restrict__ conv3_w, float* __restrict__ out) {
    extern __shared__ float sm[];
    float* w3s   = sm;
    float* ptile = w3s + F2c * F2c * K3c;
    float* ytile = ptile + F2c * 40;

    const int tid = threadIdx.x;
    const int b = blockIdx.x;
    const int tile = blockIdx.y;
    const int tc0 = tile * 24;

    for (int i = tid; i < F2c * F2c * K3c; i += 256) w3s[i] = conv3_w[i];
    for (int i = tid; i < F2c * 40; i += 256) {
        int fi = i & 31, j = i >> 5;
        int tc = tc0 - 7 + j;
        float val = 0.f;
        if (j < 39 && tc >= 0 && tc < TP) {
            float scv = d_scale2[fi], shv = d_shift2[fi];
            float s = 0.f;
            #pragma unroll
            for (int r = 0; r < 8; r++) {
                float gv = fmaf(scv, d_gbuf[(b * Tc + tc * 8 + r) * 32 + fi], shv);
                s += gv > 0.f ? gv : (__expf(gv) - 1.f);
            }
            val = s * 0.125f;
        }
        ptile[fi * 40 + j] = val;
    }
    __syncthreads();

    for (int oidx = tid; oidx < F2c * 24; oidx += 256) {
        int fo = oidx / 24;
        int tcl = oidx - fo * 24;
        float acc = 0.f;
        for (int fi = 0; fi < F2c; fi++) {
            const float* wr = w3s + (fo * 32 + fi) * 16;
            const float* pr = ptile + fi * 40 + tcl;
            #pragma unroll
            for (int k = 0; k < K3c; k++) acc = fmaf(wr[k], pr[k], acc);
        }
        float z = fmaf(d_scale3[fo], acc, d_shift3[fo]);
        z = z > 0.f ? z : (__expf(z) - 1.f);
        ytile[fo * 24 + tcl] = z;
    }
    __syncthreads();

    for (int i = tid; i < F2c * 6; i += 256) {
        int fo = i / 6, tl = i - fo * 6;
        const float* yr = ytile + fo * 24 + tl * 4;
        float s = 0.25f * (yr[0] + yr[1] + yr[2] + yr[3]);
        out[(b * 32 + fo) * 48 + tile * 6 + tl] = s;
    }
}

// ---------------- launch ----------------
extern "C" void kernel_launch(void* const* d_in, const int* in_sizes, int n_in,
                              void* d_out, int out_size) {
    const float* x        = (const float*)d_in[0];
    const float* conv1_w  = (const float*)d_in[1];
    const float* bn1_g    = (const float*)d_in[2];
    const float* bn1_b    = (const float*)d_in[3];
    const float* bn1_m    = (const float*)d_in[4];
    const float* bn1_v    = (const float*)d_in[5];
    const float* gat_w    = (const float*)d_in[6];
    const float* gat_asrc = (const float*)d_in[7];
    const float* gat_adst = (const float*)d_in[8];
    const float* gat_bias = (const float*)d_in[9];
    const float* bn2_g    = (const float*)d_in[10];
    const float* bn2_b    = (const float*)d_in[11];
    const float* bn2_m    = (const float*)d_in[12];
    const float* bn2_v    = (const float*)d_in[13];
    const float* conv3_w  = (const float*)d_in[14];
    const float* bn3_g    = (const float*)d_in[15];
    const float* bn3_b    = (const float*)d_in[16];
    const float* bn3_m    = (const float*)d_in[17];
    const float* bn3_v    = (const float*)d_in[18];
    const int*   edge_idx = (const int*)d_in[19];
    int E = in_sizes[19] / 2;
    if (E > EMAX) E = EMAX;

    cudaFuncSetAttribute(main_kernel, cudaFuncAttributeMaxDynamicSharedMemorySize, MAIN_SMEM);
    cudaFuncSetAttribute(tail_kernel, cudaFuncAttributeMaxDynamicSharedMemorySize, TAIL_SMEM);

    setup_kernel<<<1, 256>>>(conv1_w, bn1_g, bn1_b, bn1_m, bn1_v, gat_w,
                             bn2_g, bn2_b, bn2_m, bn2_v,
                             bn3_g, bn3_b, bn3_m, bn3_v, edge_idx, E);
    main_kernel<<<Bc * (Tc / NG), 256, MAIN_SMEM>>>(x, gat_asrc, gat_adst, gat_bias, E);
    tail_kernel<<<dim3(Bc, 8), 256, TAIL_SMEM>>>(conv3_w, (float*)d_out);
}